// round 1
// baseline (speedup 1.0000x reference)
#include <cuda_runtime.h>
#include <math.h>

// DiffJPEG fused kernel: one CTA (256 thr) per 16x16 tile.
// Tile = 4 Y blocks (8x8) + 1 Cb + 1 Cr block (after 2x2 pooling).
// Pipeline: load RGB -> YCbCr (+shfl 2x2 pool) -> separable DCT ->
// diff_round quant/dequant -> separable IDCT -> upsample -> RGB -> clip -> store.

#define HW 262144      // 512*512
#define W  512

__global__ __launch_bounds__(256, 8)
void diffjpeg_kernel(const float* __restrict__ img,
                     const float* __restrict__ ytab,
                     const float* __restrict__ ctab,
                     float* __restrict__ out)
{
    // sIn/sTmp: 6 blocks (0-3 = Y, 4 = Cb, 5 = Cr), 8x8 padded to row stride 9
    __shared__ float sC[64];          // C[x][u] = cos((2x+1)u*pi/16), stored [x*8+u]
    __shared__ float sIn[6][72];
    __shared__ float sTmp[6][72];
    __shared__ float sTabS[2][64];    // table * 0.4
    __shared__ float sTabR[2][64];    // 1 / (table * 0.4)

    const int tid = threadIdx.x;

    if (tid < 64) {
        int x = tid >> 3, u = tid & 7;
        sC[tid] = cospif((float)((2 * x + 1) * u) / 16.0f);
        float yv = ytab[tid] * 0.4f;
        float cv = ctab[tid] * 0.4f;
        sTabS[0][tid] = yv;  sTabR[0][tid] = 1.0f / yv;
        sTabS[1][tid] = cv;  sTabR[1][tid] = 1.0f / cv;
    }

    const int tile = blockIdx.x;
    const int b  = tile >> 10;        // 1024 tiles / image
    const int t  = tile & 1023;
    const int tY = t >> 5, tX = t & 31;
    const int ty = tid >> 4, tx = tid & 15;
    const int row = tY * 16 + ty, col = tX * 16 + tx;

    const float* base = img + (size_t)b * 3 * HW + row * W + col;
    float r  = base[0]      * 255.0f;
    float g  = base[HW]     * 255.0f;
    float bl = base[2 * HW] * 255.0f;

    float y  =  0.299f    * r + 0.587f    * g + 0.114f    * bl;
    float cb = -0.168736f * r - 0.331264f * g + 0.5f      * bl;  // centered (the +128/-128 cancel)
    float cr =  0.5f      * r - 0.418688f * g - 0.081312f * bl;

    // Y blocks: store y - 128
    sIn[(ty >> 3) * 2 + (tx >> 3)][(ty & 7) * 9 + (tx & 7)] = y - 128.0f;

    // 2x2 chroma pooling via warp shuffles: lane^1 = x-neighbor, lane^16 = y-neighbor
    float cbs = cb;
    cbs += __shfl_xor_sync(0xffffffffu, cbs, 1);
    cbs += __shfl_xor_sync(0xffffffffu, cbs, 16);
    float crs = cr;
    crs += __shfl_xor_sync(0xffffffffu, crs, 1);
    crs += __shfl_xor_sync(0xffffffffu, crs, 16);
    if (((tx | ty) & 1) == 0) {
        sIn[4][(ty >> 1) * 9 + (tx >> 1)] = cbs * 0.25f;
        sIn[5][(ty >> 1) * 9 + (tx >> 1)] = crs * 0.25f;
    }
    __syncthreads();

    // ---- Stage A: row DCT. tmp[u][y] = sum_x in[x][y] * C[x][u] ----
    #pragma unroll
    for (int e = tid; e < 384; e += 256) {
        int blk = e >> 6, rr = (e >> 3) & 7, cc = e & 7;   // rr=u, cc=y
        float s = 0.0f;
        #pragma unroll
        for (int x = 0; x < 8; x++)
            s = fmaf(sIn[blk][x * 9 + cc], sC[x * 8 + rr], s);
        sTmp[blk][rr * 9 + cc] = s;
    }
    __syncthreads();

    // ---- Stage B: col DCT + quantize (diff_round) + dequantize ----
    #pragma unroll
    for (int e = tid; e < 384; e += 256) {
        int blk = e >> 6, rr = (e >> 3) & 7, cc = e & 7;   // rr=u, cc=v
        float s = 0.0f;
        #pragma unroll
        for (int yy = 0; yy < 8; yy++)
            s = fmaf(sTmp[blk][rr * 9 + yy], sC[yy * 8 + cc], s);
        float au = rr ? 1.0f : 0.70710678118654752f;
        float av = cc ? 1.0f : 0.70710678118654752f;
        float aa = au * av;
        float D  = s * (0.25f * aa);
        int   ti = (blk < 4) ? 0 : 1;
        float tq = D * sTabR[ti][rr * 8 + cc];
        float rq = rintf(tq);                 // round half-to-even == jnp.round
        float dq = tq - rq;
        float q  = rq + dq * dq * dq;         // diff_round
        sIn[blk][rr * 9 + cc] = q * sTabS[ti][rr * 8 + cc] * aa;
    }
    __syncthreads();

    // ---- Stage A': row IDCT. t2[x][v] = sum_u d2[u][v] * C[x][u] ----
    #pragma unroll
    for (int e = tid; e < 384; e += 256) {
        int blk = e >> 6, rr = (e >> 3) & 7, cc = e & 7;   // rr=x, cc=v
        float s = 0.0f;
        #pragma unroll
        for (int u = 0; u < 8; u++)
            s = fmaf(sIn[blk][u * 9 + cc], sC[rr * 8 + u], s);
        sTmp[blk][rr * 9 + cc] = s;
    }
    __syncthreads();

    // ---- Stage B': col IDCT. out[x][y] = 0.25 * sum_v t2[x][v] * C[y][v] (+128 for Y) ----
    #pragma unroll
    for (int e = tid; e < 384; e += 256) {
        int blk = e >> 6, rr = (e >> 3) & 7, cc = e & 7;   // rr=x, cc=y
        float s = 0.0f;
        #pragma unroll
        for (int v = 0; v < 8; v++)
            s = fmaf(sTmp[blk][rr * 9 + v], sC[cc * 8 + v], s);
        sIn[blk][rr * 9 + cc] = 0.25f * s + ((blk < 4) ? 128.0f : 0.0f);
    }
    __syncthreads();

    // ---- Reconstruct pixel, YCbCr -> RGB, clip, store ----
    float yv2 = sIn[(ty >> 3) * 2 + (tx >> 3)][(ty & 7) * 9 + (tx & 7)];
    float cbv = sIn[4][(ty >> 1) * 9 + (tx >> 1)];   // already centered
    float crv = sIn[5][(ty >> 1) * 9 + (tx >> 1)];

    float ro = yv2 + 1.402f    * crv;
    float go = yv2 - 0.344136f * cbv - 0.714136f * crv;
    float bo = yv2 + 1.772f    * cbv;

    const float inv255 = 1.0f / 255.0f;
    ro = fminf(fmaxf(ro, 0.0f), 255.0f) * inv255;
    go = fminf(fmaxf(go, 0.0f), 255.0f) * inv255;
    bo = fminf(fmaxf(bo, 0.0f), 255.0f) * inv255;

    float* ob = out + (size_t)b * 3 * HW + row * W + col;
    ob[0]      = ro;
    ob[HW]     = go;
    ob[2 * HW] = bo;
}

extern "C" void kernel_launch(void* const* d_in, const int* in_sizes, int n_in,
                              void* d_out, int out_size)
{
    const float* img  = (const float*)d_in[0];
    const float* ytab = (const float*)d_in[1];
    const float* ctab = (const float*)d_in[2];
    float* out = (float*)d_out;

    // 32 images * (512/16)^2 tiles = 32768 CTAs
    diffjpeg_kernel<<<32768, 256>>>(img, ytab, ctab, out);
}

// round 2
// speedup vs baseline: 2.9274x; 2.9274x over previous
#include <cuda_runtime.h>

#define HW 262144      // 512*512
#define W  512

// cos(k*pi/16)
#define C1f 0.98078528040323044913f
#define C2f 0.92387953251128675613f
#define C3f 0.83146961230254523708f
#define C4f 0.70710678118654752440f
#define C5f 0.55557023301960222474f
#define C6f 0.38268343236508977173f
#define C7f 0.19509032201612826785f

// out[u] = sum_x in[x] * cos((2x+1)u pi/16)   (raw, unscaled)
__device__ __forceinline__ void dct8(const float* in, float* o) {
    float s0 = in[0] + in[7], s1 = in[1] + in[6];
    float s2 = in[2] + in[5], s3 = in[3] + in[4];
    float d0 = in[0] - in[7], d1 = in[1] - in[6];
    float d2 = in[2] - in[5], d3 = in[3] - in[4];
    float f0 = s0 + s3, f1 = s1 + s2;
    float e0 = s0 - s3, e1 = s1 - s2;
    o[0] = f0 + f1;
    o[4] = (f0 - f1) * C4f;
    o[2] = fmaf(e0, C2f,  e1 * C6f);
    o[6] = fmaf(e0, C6f, -e1 * C2f);
    o[1] = fmaf(d0, C1f, fmaf(d1,  C3f, fmaf(d2,  C5f,  d3 * C7f)));
    o[3] = fmaf(d0, C3f, fmaf(d1, -C7f, fmaf(d2, -C1f, -d3 * C5f)));
    o[5] = fmaf(d0, C5f, fmaf(d1, -C1f, fmaf(d2,  C7f,  d3 * C3f)));
    o[7] = fmaf(d0, C7f, fmaf(d1, -C5f, fmaf(d2,  C3f, -d3 * C1f)));
}

// out[x] = sum_u in[u] * cos((2x+1)u pi/16)   (raw, unscaled)
__device__ __forceinline__ void idct8(const float* in, float* o) {
    float E0 = fmaf(in[2],  C2f, fmaf(in[4],  C4f, fmaf(in[6],  C6f, in[0])));
    float E1 = fmaf(in[2],  C6f, fmaf(in[4], -C4f, fmaf(in[6], -C2f, in[0])));
    float E2 = fmaf(in[2], -C6f, fmaf(in[4], -C4f, fmaf(in[6],  C2f, in[0])));
    float E3 = fmaf(in[2], -C2f, fmaf(in[4],  C4f, fmaf(in[6], -C6f, in[0])));
    float O0 = fmaf(in[1],  C1f, fmaf(in[3],  C3f, fmaf(in[5],  C5f,  in[7] * C7f)));
    float O1 = fmaf(in[1],  C3f, fmaf(in[3], -C7f, fmaf(in[5], -C1f, -in[7] * C5f)));
    float O2 = fmaf(in[1],  C5f, fmaf(in[3], -C1f, fmaf(in[5],  C7f,  in[7] * C3f)));
    float O3 = fmaf(in[1],  C7f, fmaf(in[3], -C5f, fmaf(in[5],  C3f, -in[7] * C1f)));
    o[0] = E0 + O0;  o[7] = E0 - O0;
    o[1] = E1 + O1;  o[6] = E1 - O1;
    o[2] = E2 + O2;  o[5] = E2 - O2;
    o[3] = E3 + O3;  o[4] = E3 - O3;
}

__global__ __launch_bounds__(256)
void diffjpeg_kernel(const float* __restrict__ img,
                     const float* __restrict__ ytab,
                     const float* __restrict__ ctab,
                     float* __restrict__ out)
{
    // pixel planes, padded strides (33 / 17) for conflict-free row access
    __shared__ float sY [32 * 33];
    __shared__ float sCb[16 * 17];
    __shared__ float sCr[16 * 17];
    // transpose scratch: 24 blocks, stride 72, XOR-swizzled rows
    __shared__ float sT [24 * 72];
    // premultiplied quant tables: R = 0.25*aa/(0.4*tab), S = 0.25*aa*0.4*tab
    __shared__ float sR[2][64];
    __shared__ float sS[2][64];

    const int tid = threadIdx.x;

    if (tid < 128) {
        int ti = tid >> 6, i = tid & 63;
        int u = i >> 3, v = i & 7;
        float aa = (u ? 1.0f : C4f) * (v ? 1.0f : C4f);
        float tq = (ti ? ctab[i] : ytab[i]) * 0.4f;
        sR[ti][i] = 0.25f * aa / tq;
        sS[ti][i] = 0.25f * aa * tq;
    }

    // ---------------- front end: load RGB, YCbCr, 2x2 chroma pool ----------
    const int tile = blockIdx.x;
    const int bimg = tile >> 8;            // 256 tiles per image
    const int t    = tile & 255;
    const int ty   = tid >> 3;             // 0..31
    const int txq  = tid & 7;              // 0..7 (x in float4 units)
    const int grow = (t >> 4) * 32 + ty;
    const int gcol = (t & 15) * 32 + txq * 4;

    const float* p = img + (size_t)bimg * 3 * HW + grow * W + gcol;
    float4 r4 = *(const float4*)p;
    float4 g4 = *(const float4*)(p + HW);
    float4 b4 = *(const float4*)(p + 2 * HW);

    float rr[4] = {r4.x, r4.y, r4.z, r4.w};
    float gg[4] = {g4.x, g4.y, g4.z, g4.w};
    float bb[4] = {b4.x, b4.y, b4.z, b4.w};

    float yv[4], cbv[4], crv[4];
    #pragma unroll
    for (int j = 0; j < 4; j++) {
        // coefficients pre-multiplied by 255; Y centered (-128)
        yv [j] = fmaf(rr[j],  76.245f,   fmaf(gg[j],  149.685f,  fmaf(bb[j],  29.07f,    -128.0f)));
        cbv[j] = fmaf(rr[j], -43.02768f, fmaf(gg[j], -84.47232f,       bb[j] * 127.5f));
        crv[j] = fmaf(rr[j], 127.5f,     fmaf(gg[j], -106.76544f,     bb[j] * -20.73456f));
    }

    #pragma unroll
    for (int j = 0; j < 4; j++)
        sY[ty * 33 + txq * 4 + j] = yv[j];

    // horizontal pair sums in-thread, vertical partner via shfl (row ty^1 = tid^8)
    float cb0 = cbv[0] + cbv[1], cb1 = cbv[2] + cbv[3];
    float cr0 = crv[0] + crv[1], cr1 = crv[2] + crv[3];
    float cb0o = __shfl_xor_sync(0xffffffffu, cb0, 8);
    float cb1o = __shfl_xor_sync(0xffffffffu, cb1, 8);
    float cr0o = __shfl_xor_sync(0xffffffffu, cr0, 8);
    float cr1o = __shfl_xor_sync(0xffffffffu, cr1, 8);
    if (!(ty & 1)) {
        int ci = (ty >> 1) * 17 + txq * 2;
        sCb[ci]     = 0.25f * (cb0 + cb0o);
        sCb[ci + 1] = 0.25f * (cb1 + cb1o);
        sCr[ci]     = 0.25f * (cr0 + cr0o);
        sCr[ci + 1] = 0.25f * (cr1 + cr1o);
    }
    __syncthreads();

    // ---------------- transforms: thread = (block, row) --------------------
    // blocks 0..15 = Y (4x4), 16..19 = Cb (2x2), 20..23 = Cr (2x2)
    float* plane = 0;
    int poff = 0, ti = 0;
    const int blk = tid >> 3, r = tid & 7;
    const bool act = (tid < 192);
    if (act) {
        if (blk < 16) {
            int by = blk >> 2, bx = blk & 3;
            plane = sY;  poff = (by * 8 + r) * 33 + bx * 8;  ti = 0;
        } else {
            int bc = blk & 3;                 // (blk-16)&3 / (blk-20)&3
            int by = bc >> 1, bx = bc & 1;
            plane = (blk < 20) ? sCb : sCr;
            poff = (by * 8 + r) * 17 + bx * 8;  ti = 1;
        }
    }
    const int tb = blk * 72;

    float a[8], o[8];

    // stage 1: row DCT (registers), write T rows swizzled
    if (act) {
        #pragma unroll
        for (int c = 0; c < 8; c++) a[c] = plane[poff + c];
        dct8(a, o);
        #pragma unroll
        for (int c = 0; c < 8; c++) sT[tb + r * 8 + (c ^ r)] = o[c];
    }
    __syncthreads();

    // stage 2+3: column DCT, quant/dequant (diff_round), column IDCT.
    // thread owns column v=r; reads+writes only its own swizzled addresses.
    if (act) {
        const int v = r;
        #pragma unroll
        for (int x = 0; x < 8; x++) a[x] = sT[tb + x * 8 + (v ^ x)];
        dct8(a, o);
        #pragma unroll
        for (int u = 0; u < 8; u++) {
            float tq = o[u] * sR[ti][u * 8 + v];
            float rq = rintf(tq);            // round-half-even == jnp.round
            float dq = tq - rq;
            a[u] = (rq + dq * dq * dq) * sS[ti][u * 8 + v];
        }
        idct8(a, o);                          // o[x] = U[x][v]
        #pragma unroll
        for (int x = 0; x < 8; x++) sT[tb + x * 8 + (v ^ x)] = o[x];
    }
    __syncthreads();

    // stage 4: row IDCT, write reconstructed rows back to planes (centered)
    if (act) {
        #pragma unroll
        for (int v = 0; v < 8; v++) a[v] = sT[tb + r * 8 + (v ^ r)];
        idct8(a, o);
        #pragma unroll
        for (int c = 0; c < 8; c++) plane[poff + c] = o[c];
    }
    __syncthreads();

    // ---------------- back end: upsample, YCbCr->RGB, clip, store ----------
    float4 orv, ogv, obv;
    float* po_r = &orv.x;
    float* po_g = &ogv.x;
    float* po_b = &obv.x;
    const int ci = (ty >> 1) * 17 + txq * 2;
    float cbl[2] = { sCb[ci], sCb[ci + 1] };
    float crl[2] = { sCr[ci], sCr[ci + 1] };
    #pragma unroll
    for (int j = 0; j < 4; j++) {
        float yb = sY[ty * 33 + txq * 4 + j] + 128.0f;
        float cc = cbl[j >> 1], cr = crl[j >> 1];
        float ro = fmaf(cr,  1.402f,    yb);
        float go = fmaf(cr, -0.714136f, fmaf(cc, -0.344136f, yb));
        float bo = fmaf(cc,  1.772f,    yb);
        const float inv255 = 1.0f / 255.0f;
        po_r[j] = fminf(fmaxf(ro, 0.0f), 255.0f) * inv255;
        po_g[j] = fminf(fmaxf(go, 0.0f), 255.0f) * inv255;
        po_b[j] = fminf(fmaxf(bo, 0.0f), 255.0f) * inv255;
    }
    float* q = out + (size_t)bimg * 3 * HW + grow * W + gcol;
    *(float4*)q            = orv;
    *(float4*)(q + HW)     = ogv;
    *(float4*)(q + 2 * HW) = obv;
}

extern "C" void kernel_launch(void* const* d_in, const int* in_sizes, int n_in,
                              void* d_out, int out_size)
{
    const float* img  = (const float*)d_in[0];
    const float* ytab = (const float*)d_in[1];
    const float* ctab = (const float*)d_in[2];
    float* out = (float*)d_out;

    // 32 images * (512/32)^2 tiles = 8192 CTAs
    diffjpeg_kernel<<<8192, 256>>>(img, ytab, ctab, out);
}

// round 3
// speedup vs baseline: 3.0796x; 1.0520x over previous
#include <cuda_runtime.h>

#define HW 262144      // 512*512
#define W  512

// cos(k*pi/16)
#define C1f 0.98078528040323044913f
#define C2f 0.92387953251128675613f
#define C3f 0.83146961230254523708f
#define C4f 0.70710678118654752440f
#define C5f 0.55557023301960222474f
#define C6f 0.38268343236508977173f
#define C7f 0.19509032201612826785f

// out[u] = sum_x in[x] * cos((2x+1)u pi/16)   (raw, unscaled)
__device__ __forceinline__ void dct8(const float* in, float* o) {
    float s0 = in[0] + in[7], s1 = in[1] + in[6];
    float s2 = in[2] + in[5], s3 = in[3] + in[4];
    float d0 = in[0] - in[7], d1 = in[1] - in[6];
    float d2 = in[2] - in[5], d3 = in[3] - in[4];
    float f0 = s0 + s3, f1 = s1 + s2;
    float e0 = s0 - s3, e1 = s1 - s2;
    o[0] = f0 + f1;
    o[4] = (f0 - f1) * C4f;
    o[2] = fmaf(e0, C2f,  e1 * C6f);
    o[6] = fmaf(e0, C6f, -e1 * C2f);
    o[1] = fmaf(d0, C1f, fmaf(d1,  C3f, fmaf(d2,  C5f,  d3 * C7f)));
    o[3] = fmaf(d0, C3f, fmaf(d1, -C7f, fmaf(d2, -C1f, -d3 * C5f)));
    o[5] = fmaf(d0, C5f, fmaf(d1, -C1f, fmaf(d2,  C7f,  d3 * C3f)));
    o[7] = fmaf(d0, C7f, fmaf(d1, -C5f, fmaf(d2,  C3f, -d3 * C1f)));
}

// out[x] = sum_u in[u] * cos((2x+1)u pi/16)   (raw, unscaled)
__device__ __forceinline__ void idct8(const float* in, float* o) {
    float E0 = fmaf(in[2],  C2f, fmaf(in[4],  C4f, fmaf(in[6],  C6f, in[0])));
    float E1 = fmaf(in[2],  C6f, fmaf(in[4], -C4f, fmaf(in[6], -C2f, in[0])));
    float E2 = fmaf(in[2], -C6f, fmaf(in[4], -C4f, fmaf(in[6],  C2f, in[0])));
    float E3 = fmaf(in[2], -C2f, fmaf(in[4],  C4f, fmaf(in[6], -C6f, in[0])));
    float O0 = fmaf(in[1],  C1f, fmaf(in[3],  C3f, fmaf(in[5],  C5f,  in[7] * C7f)));
    float O1 = fmaf(in[1],  C3f, fmaf(in[3], -C7f, fmaf(in[5], -C1f, -in[7] * C5f)));
    float O2 = fmaf(in[1],  C5f, fmaf(in[3], -C1f, fmaf(in[5],  C7f,  in[7] * C3f)));
    float O3 = fmaf(in[1],  C7f, fmaf(in[3], -C5f, fmaf(in[5],  C3f, -in[7] * C1f)));
    o[0] = E0 + O0;  o[7] = E0 - O0;
    o[1] = E1 + O1;  o[6] = E1 - O1;
    o[2] = E2 + O2;  o[5] = E2 - O2;
    o[3] = E3 + O3;  o[4] = E3 - O3;
}

__global__ __launch_bounds__(256)
void diffjpeg_kernel(const float* __restrict__ img,
                     const float* __restrict__ ytab,
                     const float* __restrict__ ctab,
                     float* __restrict__ out)
{
    // pixel planes: strides multiple of 4 (16B-aligned rows) AND conflict-free
    __shared__ float sY [32 * 36];     // stride 36
    __shared__ float sCb[16 * 20];     // stride 20
    __shared__ float sCr[16 * 20];
    // transpose scratch: 24 blocks * 72, row stride 9 (conflict-free, scalar)
    __shared__ float sT [24 * 72];
    // interleaved quant tables: [2i] = 0.25*aa/(0.4*tab), [2i+1] = 0.25*aa*0.4*tab
    __shared__ float sRS[2][128];

    const int tid = threadIdx.x;

    if (tid < 128) {
        int ti = tid >> 6, i = tid & 63;
        int u = i >> 3, v = i & 7;
        float aa = (u ? 1.0f : C4f) * (v ? 1.0f : C4f);
        float tq = (ti ? ctab[i] : ytab[i]) * 0.4f;
        sRS[ti][2 * i]     = 0.25f * aa / tq;
        sRS[ti][2 * i + 1] = 0.25f * aa * tq;
    }

    // ---------------- front end: load RGB, YCbCr, 2x2 chroma pool ----------
    const int tile = blockIdx.x;
    const int bimg = tile >> 8;            // 256 tiles per image
    const int t    = tile & 255;
    const int ty   = tid >> 3;             // 0..31
    const int txq  = tid & 7;              // 0..7 (x in float4 units)
    const int grow = (t >> 4) * 32 + ty;
    const int gcol = (t & 15) * 32 + txq * 4;

    const float* p = img + (size_t)bimg * 3 * HW + grow * W + gcol;
    float4 r4 = *(const float4*)p;
    float4 g4 = *(const float4*)(p + HW);
    float4 b4 = *(const float4*)(p + 2 * HW);

    float rr[4] = {r4.x, r4.y, r4.z, r4.w};
    float gg[4] = {g4.x, g4.y, g4.z, g4.w};
    float bb[4] = {b4.x, b4.y, b4.z, b4.w};

    float yv[4], cbv[4], crv[4];
    #pragma unroll
    for (int j = 0; j < 4; j++) {
        // coefficients pre-multiplied by 255; Y centered (-128)
        yv [j] = fmaf(rr[j],  76.245f,   fmaf(gg[j],  149.685f,  fmaf(bb[j],  29.07f,    -128.0f)));
        cbv[j] = fmaf(rr[j], -43.02768f, fmaf(gg[j], -84.47232f,       bb[j] * 127.5f));
        crv[j] = fmaf(rr[j], 127.5f,     fmaf(gg[j], -106.76544f,     bb[j] * -20.73456f));
    }

    *(float4*)&sY[ty * 36 + txq * 4] = make_float4(yv[0], yv[1], yv[2], yv[3]);

    // horizontal pair sums in-thread, vertical partner via shfl (row ty^1 = tid^8)
    float cb0 = cbv[0] + cbv[1], cb1 = cbv[2] + cbv[3];
    float cr0 = crv[0] + crv[1], cr1 = crv[2] + crv[3];
    float cb0o = __shfl_xor_sync(0xffffffffu, cb0, 8);
    float cb1o = __shfl_xor_sync(0xffffffffu, cb1, 8);
    float cr0o = __shfl_xor_sync(0xffffffffu, cr0, 8);
    float cr1o = __shfl_xor_sync(0xffffffffu, cr1, 8);
    if (!(ty & 1)) {
        int ci = (ty >> 1) * 20 + txq * 2;
        *(float2*)&sCb[ci] = make_float2(0.25f * (cb0 + cb0o), 0.25f * (cb1 + cb1o));
        *(float2*)&sCr[ci] = make_float2(0.25f * (cr0 + cr0o), 0.25f * (cr1 + cr1o));
    }
    __syncthreads();

    // ---------------- transforms: thread = (block, row) --------------------
    // blocks 0..15 = Y (4x4), 16..19 = Cb (2x2), 20..23 = Cr (2x2)
    float* plane = sY;
    int poff = 0, ti = 0;
    const int blk = tid >> 3, r = tid & 7;
    const bool act = (tid < 192);
    if (act) {
        if (blk < 16) {
            int by = blk >> 2, bx = blk & 3;
            plane = sY;  poff = (by * 8 + r) * 36 + bx * 8;  ti = 0;
        } else {
            int bc = blk & 3;
            int by = bc >> 1, bx = bc & 1;
            plane = (blk < 20) ? sCb : sCr;
            poff = (by * 8 + r) * 20 + bx * 8;  ti = 1;
        }
    }
    float* const trow = &sT[blk * 72 + r * 9];   // row base (stage 1 write, 4 read)
    float* const tcol = &sT[blk * 72 + r];       // column base (stage 2/3), v = r

    float a[8], o[8];

    // stage 1: row DCT (registers), vector loads from plane, scalar row write
    if (act) {
        float4 v0 = *(const float4*)&plane[poff];
        float4 v1 = *(const float4*)&plane[poff + 4];
        a[0] = v0.x; a[1] = v0.y; a[2] = v0.z; a[3] = v0.w;
        a[4] = v1.x; a[5] = v1.y; a[6] = v1.z; a[7] = v1.w;
        dct8(a, o);
        #pragma unroll
        for (int c = 0; c < 8; c++) trow[c] = o[c];
    }
    __syncthreads();

    // stage 2+3: column DCT, quant/dequant (diff_round), column IDCT
    if (act) {
        #pragma unroll
        for (int x = 0; x < 8; x++) a[x] = tcol[9 * x];
        dct8(a, o);
        const float* pT = &sRS[ti][2 * r];
        #pragma unroll
        for (int u = 0; u < 8; u++) {
            float2 rs = *(const float2*)&pT[16 * u];
            float tq = o[u] * rs.x;
            float rq = rintf(tq);            // round-half-even == jnp.round
            float dq = tq - rq;
            a[u] = (rq + dq * dq * dq) * rs.y;
        }
        idct8(a, o);                          // o[x] = recon column v
        #pragma unroll
        for (int x = 0; x < 8; x++) tcol[9 * x] = o[x];
    }
    __syncthreads();

    // stage 4: row IDCT, vector stores back to plane (centered values)
    if (act) {
        #pragma unroll
        for (int v = 0; v < 8; v++) a[v] = trow[v];
        idct8(a, o);
        *(float4*)&plane[poff]     = make_float4(o[0], o[1], o[2], o[3]);
        *(float4*)&plane[poff + 4] = make_float4(o[4], o[5], o[6], o[7]);
    }
    __syncthreads();

    // ---------------- back end: upsample, YCbCr->RGB, clip, store ----------
    float4 yq = *(const float4*)&sY[ty * 36 + txq * 4];
    const int ci = (ty >> 1) * 20 + txq * 2;
    float2 cbl = *(const float2*)&sCb[ci];
    float2 crl = *(const float2*)&sCr[ci];

    float yb[4] = {yq.x + 128.0f, yq.y + 128.0f, yq.z + 128.0f, yq.w + 128.0f};
    float cbp[4] = {cbl.x, cbl.x, cbl.y, cbl.y};
    float crp[4] = {crl.x, crl.x, crl.y, crl.y};

    float4 orv, ogv, obv;
    float* po_r = &orv.x;
    float* po_g = &ogv.x;
    float* po_b = &obv.x;
    #pragma unroll
    for (int j = 0; j < 4; j++) {
        float ro = fmaf(crp[j],  1.402f,    yb[j]);
        float go = fmaf(crp[j], -0.714136f, fmaf(cbp[j], -0.344136f, yb[j]));
        float bo = fmaf(cbp[j],  1.772f,    yb[j]);
        const float inv255 = 1.0f / 255.0f;
        po_r[j] = fminf(fmaxf(ro, 0.0f), 255.0f) * inv255;
        po_g[j] = fminf(fmaxf(go, 0.0f), 255.0f) * inv255;
        po_b[j] = fminf(fmaxf(bo, 0.0f), 255.0f) * inv255;
    }
    float* q = out + (size_t)bimg * 3 * HW + grow * W + gcol;
    *(float4*)q            = orv;
    *(float4*)(q + HW)     = ogv;
    *(float4*)(q + 2 * HW) = obv;
}

extern "C" void kernel_launch(void* const* d_in, const int* in_sizes, int n_in,
                              void* d_out, int out_size)
{
    const float* img  = (const float*)d_in[0];
    const float* ytab = (const float*)d_in[1];
    const float* ctab = (const float*)d_in[2];
    float* out = (float*)d_out;

    // 32 images * (512/32)^2 tiles = 8192 CTAs
    diffjpeg_kernel<<<8192, 256>>>(img, ytab, ctab, out);
}